// round 13
// baseline (speedup 1.0000x reference)
#include <cuda_runtime.h>
#include <cuda_bf16.h>
#include <cstdint>

typedef unsigned long long ull;

#define BATCH 4
#define CH    64
#define HW    64
#define NPIX  4096
#define EPSBN 1e-5f
#define LOG2E_F 1.4426950408889634f

// ---------------------------------------------------------------------------
// Scratch
// ---------------------------------------------------------------------------
__device__ float g_c1raw[BATCH * CH * NPIX];
__device__ float g_z    [BATCH * CH * NPIX];
__device__ float g_mean[CH];
__device__ float g_rstd[CH];
__device__ float g_stats[2 * CH];
__device__ float g_ypart[2 * BATCH * CH * NPIX];   // partial y sums (unscaled)
__device__ float g_rspart[2 * BATCH * NPIX];       // partial rowsums
__device__ __nv_bfloat16 g_wmma[5 * 9 * 2 * CH * CH];   // [set][tap][hi/lo][co][ci]

// bf16 operands for mma.sync
__device__ __nv_bfloat16 g_thT_hi[BATCH * NPIX * CH];   // [b][n][c] (pre-scaled by log2e)
__device__ __nv_bfloat16 g_thT_lo[BATCH * NPIX * CH];
__device__ __nv_bfloat16 g_phT_hi[BATCH * NPIX * CH];   // [b][m][c]
__device__ __nv_bfloat16 g_phT_lo[BATCH * NPIX * CH];
__device__ __nv_bfloat16 g_g_hi [BATCH * CH * NPIX];    // [b][c][m]
__device__ __nv_bfloat16 g_g_lo [BATCH * CH * NPIX];

// ---------------------------------------------------------------------------
// f32x2 helpers
// ---------------------------------------------------------------------------
__device__ __forceinline__ ull pk2(float lo, float hi) {
    ull r; asm("mov.b64 %0, {%1, %2};" : "=l"(r) : "f"(lo), "f"(hi)); return r;
}
__device__ __forceinline__ void fma2(ull& d, ull a, ull b) {
    asm("fma.rn.f32x2 %0, %1, %2, %0;" : "+l"(d) : "l"(a), "l"(b));
}
__device__ __forceinline__ float2 upk2(ull v) {
    float2 r; asm("mov.b64 {%0, %1}, %2;" : "=f"(r.x), "=f"(r.y) : "l"(v)); return r;
}
__device__ __forceinline__ float ex2f(float x) {
    float r; asm("ex2.approx.f32 %0, %1;" : "=f"(r) : "f"(x)); return r;
}

// ---------------------------------------------------------------------------
// mma.sync / cp.async helpers
// ---------------------------------------------------------------------------
__device__ __forceinline__ uint32_t smem_u32(const void* p) {
    uint32_t a;
    asm("{ .reg .u64 t; cvta.to.shared.u64 t, %1; cvt.u32.u64 %0, t; }" : "=r"(a) : "l"(p));
    return a;
}
#define SW128(o) ((o) ^ ((((uint32_t)(o)) >> 3) & 0x70))

__device__ __forceinline__ void ldsm4(uint32_t* r, uint32_t addr) {
    asm volatile("ldmatrix.sync.aligned.m8n8.x4.shared.b16 {%0,%1,%2,%3}, [%4];"
        : "=r"(r[0]), "=r"(r[1]), "=r"(r[2]), "=r"(r[3]) : "r"(addr));
}
__device__ __forceinline__ void mma16816(float* d, const uint32_t* a, const uint32_t* b) {
    asm volatile("mma.sync.aligned.m16n8k16.row.col.f32.bf16.bf16.f32 "
        "{%0,%1,%2,%3},{%4,%5,%6,%7},{%8,%9},{%0,%1,%2,%3};"
        : "+f"(d[0]), "+f"(d[1]), "+f"(d[2]), "+f"(d[3])
        : "r"(a[0]), "r"(a[1]), "r"(a[2]), "r"(a[3]), "r"(b[0]), "r"(b[1]));
}
__device__ __forceinline__ void cpasync16(uint32_t dst, const void* src) {
    asm volatile("cp.async.cg.shared.global [%0], [%1], 16;" :: "r"(dst), "l"(src));
}
__device__ __forceinline__ void cpasync_commit() {
    asm volatile("cp.async.commit_group;" ::: "memory");
}
__device__ __forceinline__ void cpasync_wait0() {
    asm volatile("cp.async.wait_group 0;" ::: "memory");
}

// ---------------------------------------------------------------------------
// Weight prep: w[co][ci][kh][kw] fp32 -> [set][tap][hi/lo][co][ci] bf16
// ---------------------------------------------------------------------------
__global__ void wtrans_mma_kernel(
    const float* __restrict__ w0, const float* __restrict__ w1,
    const float* __restrict__ w2, const float* __restrict__ w3,
    const float* __restrict__ w4, __nv_bfloat16* __restrict__ wm)
{
    const float* ws[5] = {w0, w1, w2, w3, w4};
    int i = blockIdx.x * 256 + threadIdx.x;
    if (i < 5 * 9 * 4096) {
        int set = i / 36864, rem = i % 36864;
        int tap = rem / 4096, rem2 = rem % 4096;
        int co = rem2 >> 6, ci = rem2 & 63;
        int kh = tap / 3, kw = tap % 3;
        float v = ws[set][co * 576 + ci * 9 + kh * 3 + kw];
        __nv_bfloat16 h = __float2bfloat16_rn(v);
        __nv_bfloat16 l = __float2bfloat16_rn(v - __bfloat162float(h));
        size_t base = ((size_t)(set * 9 + tap) * 2) * 4096 + co * 64 + ci;
        wm[base] = h;
        wm[base + 4096] = l;
    }
}

// ---------------------------------------------------------------------------
// HMMA implicit-GEMM 3x3 conv (unchanged from R12)
// ---------------------------------------------------------------------------
#define SXT_HI 0
#define SXT_LO 38016
#define SWB0   76032
#define SWB1   85248
#define SOUT   94464
#define SBN    111872
#define CV_SMEM0 94464
#define CV_SMEM1 112384

template<int MODE>
__global__ void __launch_bounds__(256, 2) conv_mma_kernel(
    const float* __restrict__ in, const __nv_bfloat16* __restrict__ wm,
    float* __restrict__ out, float* __restrict__ stats,
    const float* __restrict__ mean, const float* __restrict__ rstd,
    const float* __restrict__ gamma, const float* __restrict__ beta,
    const float* __restrict__ thb, const float* __restrict__ phb,
    const float* __restrict__ gbias,
    __nv_bfloat16* __restrict__ thH, __nv_bfloat16* __restrict__ thL,
    __nv_bfloat16* __restrict__ phH, __nv_bfloat16* __restrict__ phL,
    __nv_bfloat16* __restrict__ gH,  __nv_bfloat16* __restrict__ gL)
{
    extern __shared__ __align__(128) char smem[];
    const uint32_t sb = smem_u32(smem);
    const int tid = threadIdx.x, w = tid >> 5, lane = tid & 31;
    const int h0 = blockIdx.x * 2;
    const int b  = blockIdx.y;
    const int co_off = blockIdx.z * 32;
    const int mpair = w & 1, nq = w >> 1;
    const int co_base = mpair * 16;

    if (MODE == 1) {
        if (tid < 64) {
            float sc = rstd[tid] * gamma[tid];
            ((float*)(smem + SBN))[tid]      = sc;
            ((float*)(smem + SBN))[64 + tid] = beta[tid] - mean[tid] * sc;
        }
        __syncthreads();
    }

    {
        const float* scl = (const float*)(smem + SBN);
        const float* shf = scl + 64;
        for (int i = tid; i < 512; i += 256) {
            int r = i >> 7, ci = (i >> 1) & 63, e = i & 1;
            uint32_t off = (uint32_t)((r * 66 + (e ? 65 : 0)) * 72 + ci) * 2;
            *(__nv_bfloat16*)(smem + SXT_HI + off) = __float2bfloat16_rn(0.f);
            *(__nv_bfloat16*)(smem + SXT_LO + off) = __float2bfloat16_rn(0.f);
        }
        #pragma unroll
        for (int j = 0; j < 16; ++j) {
            int e4 = tid + 256 * j;
            int w4 = (e4 & 15) * 4;
            int ci = (e4 >> 4) & 63;
            int ri = e4 >> 10;
            int row = h0 - 1 + ri;
            float4 v = make_float4(0.f, 0.f, 0.f, 0.f);
            if (row >= 0 && row < HW) {
                v = *(const float4*)&in[((size_t)(b * CH + ci) << 12) + row * HW + w4];
                if (MODE == 1) {
                    float s = scl[ci], t = shf[ci];
                    v.x = fmaxf(fmaf(v.x, s, t), 0.f);
                    v.y = fmaxf(fmaf(v.y, s, t), 0.f);
                    v.z = fmaxf(fmaf(v.z, s, t), 0.f);
                    v.w = fmaxf(fmaf(v.w, s, t), 0.f);
                }
            }
            const float vv[4] = {v.x, v.y, v.z, v.w};
            #pragma unroll
            for (int jj = 0; jj < 4; ++jj) {
                uint32_t off = (uint32_t)((ri * 66 + w4 + jj + 1) * 72 + ci) * 2;
                __nv_bfloat16 h = __float2bfloat16_rn(vv[jj]);
                *(__nv_bfloat16*)(smem + SXT_HI + off) = h;
                *(__nv_bfloat16*)(smem + SXT_LO + off) =
                    __float2bfloat16_rn(vv[jj] - __bfloat162float(h));
            }
        }
    }

    const int wside = tid >> 7, wco = (tid >> 2) & 31, wqtr = tid & 3;
    auto load_w = [&](int q, int buf) {
        const __nv_bfloat16* s = wm + (size_t)q * 8192 + wside * 4096
                               + (co_off + wco) * 64 + wqtr * 16;
        uint32_t d = sb + (buf ? SWB1 : SWB0) + wside * 4608
                   + (uint32_t)(wco * 72 + wqtr * 16) * 2;
        cpasync16(d, s);
        cpasync16(d + 16, s + 8);
        cpasync_commit();
    };

    const int bci  = (lane & 3) * 4;
    const int bwn  = lane >> 2;
    const int arow = ((lane & 8) ? 8 : 0) + (lane & 7);
    const int acolh = (lane & 16) ? 8 : 0;

    const int NSETS = (MODE == 1) ? 3 : 1;
    const int NT = NSETS * 9;
    load_w(0, 0);
    int q = 0;

    for (int s = 0; s < NSETS; ++s) {
        float acc[4][4];
        #pragma unroll
        for (int nt = 0; nt < 4; ++nt)
            #pragma unroll
            for (int k = 0; k < 4; ++k) acc[nt][k] = 0.f;

        for (int tap = 0; tap < 9; ++tap) {
            cpasync_wait0();
            __syncthreads();
            if (q + 1 < NT) load_w(q + 1, (q + 1) & 1);

            const int dh = tap / 3, dw = tap % 3;
            const uint32_t swb = sb + ((q & 1) ? SWB1 : SWB0);
            int bb[4];
            #pragma unroll
            for (int nt = 0; nt < 4; ++nt) {
                int p0 = nq * 32 + nt * 8;
                int r = (p0 >> 6) + dh;
                int wc = (p0 & 63) + bwn + dw;
                bb[nt] = (r * 66 + wc) * 144 + bci;
            }
            #pragma unroll
            for (int k = 0; k < 4; ++k) {
                uint32_t Ah[4], Al[4];
                uint32_t ao = (uint32_t)((co_base + arow) * 72 + k * 16 + acolh) * 2;
                ldsm4(Ah, swb + ao);
                ldsm4(Al, swb + 4608 + ao);
                #pragma unroll
                for (int nt = 0; nt < 4; ++nt) {
                    int o = bb[nt] + k * 32;
                    uint32_t bh[2], bl[2];
                    bh[0] = *(const uint32_t*)(smem + SXT_HI + o);
                    bh[1] = *(const uint32_t*)(smem + SXT_HI + o + 16);
                    bl[0] = *(const uint32_t*)(smem + SXT_LO + o);
                    bl[1] = *(const uint32_t*)(smem + SXT_LO + o + 16);
                    mma16816(acc[nt], Ah, bh);
                    mma16816(acc[nt], Al, bh);
                    mma16816(acc[nt], Ah, bl);
                }
            }
            ++q;
        }

        if (MODE == 0) {
            const int co_a = co_off + co_base + (lane >> 2);
            float sa = 0.f, qa = 0.f, sbx = 0.f, qb = 0.f;
            #pragma unroll
            for (int nt = 0; nt < 4; ++nt) {
                int gp = nq * 32 + nt * 8 + (lane & 3) * 2;
                float d0 = acc[nt][0], d1 = acc[nt][1];
                float d2 = acc[nt][2], d3 = acc[nt][3];
                *(float2*)&out[((size_t)(b * CH + co_a) << 12) + h0 * HW + gp]     = make_float2(d0, d1);
                *(float2*)&out[((size_t)(b * CH + co_a + 8) << 12) + h0 * HW + gp] = make_float2(d2, d3);
                sa += d0 + d1; qa += d0 * d0 + d1 * d1;
                sbx += d2 + d3; qb += d2 * d2 + d3 * d3;
            }
            sa += __shfl_xor_sync(0xffffffffu, sa, 1); sa += __shfl_xor_sync(0xffffffffu, sa, 2);
            qa += __shfl_xor_sync(0xffffffffu, qa, 1); qa += __shfl_xor_sync(0xffffffffu, qa, 2);
            sbx += __shfl_xor_sync(0xffffffffu, sbx, 1); sbx += __shfl_xor_sync(0xffffffffu, sbx, 2);
            qb += __shfl_xor_sync(0xffffffffu, qb, 1); qb += __shfl_xor_sync(0xffffffffu, qb, 2);
            if ((lane & 3) == 0) {
                atomicAdd(&stats[co_a], sa);      atomicAdd(&stats[CH + co_a], qa);
                atomicAdd(&stats[co_a + 8], sbx); atomicAdd(&stats[CH + co_a + 8], qb);
            }
        } else if (s == 2) {
            const int co_a = co_off + co_base + (lane >> 2);
            float bva = gbias[co_a], bvb = gbias[co_a + 8];
            #pragma unroll
            for (int nt = 0; nt < 4; ++nt) {
                int gp = nq * 32 + nt * 8 + (lane & 3) * 2;
                float d0 = acc[nt][0] + bva, d1 = acc[nt][1] + bva;
                float d2 = acc[nt][2] + bvb, d3 = acc[nt][3] + bvb;
                __nv_bfloat162 h01 = __floats2bfloat162_rn(d0, d1);
                __nv_bfloat162 h23 = __floats2bfloat162_rn(d2, d3);
                __nv_bfloat162 l01 = __floats2bfloat162_rn(d0 - __bfloat162float(h01.x),
                                                           d1 - __bfloat162float(h01.y));
                __nv_bfloat162 l23 = __floats2bfloat162_rn(d2 - __bfloat162float(h23.x),
                                                           d3 - __bfloat162float(h23.y));
                size_t oa = ((size_t)(b * CH + co_a) << 12) + h0 * HW + gp;
                size_t ob = ((size_t)(b * CH + co_a + 8) << 12) + h0 * HW + gp;
                *(__nv_bfloat162*)&gH[oa] = h01; *(__nv_bfloat162*)&gL[oa] = l01;
                *(__nv_bfloat162*)&gH[ob] = h23; *(__nv_bfloat162*)&gL[ob] = l23;
            }
        } else {
            const float* bias = s ? phb : thb;
            const float osc = s ? 1.f : LOG2E_F;
            float* so = (float*)(smem + SOUT);
            __syncthreads();
            {
                const int co_l = co_base + (lane >> 2);
                float bva = bias[co_off + co_l], bvb = bias[co_off + co_l + 8];
                #pragma unroll
                for (int nt = 0; nt < 4; ++nt) {
                    int gp = nq * 32 + nt * 8 + (lane & 3) * 2;
                    so[gp * 34 + co_l]           = (acc[nt][0] + bva) * osc;
                    so[(gp + 1) * 34 + co_l]     = (acc[nt][1] + bva) * osc;
                    so[gp * 34 + co_l + 8]       = (acc[nt][2] + bvb) * osc;
                    so[(gp + 1) * 34 + co_l + 8] = (acc[nt][3] + bvb) * osc;
                }
            }
            __syncthreads();
            {
                const int p = tid >> 1, half = tid & 1;
                const float* row = so + p * 34 + half * 16;
                __nv_bfloat16 hv[16], lv[16];
                #pragma unroll
                for (int k = 0; k < 16; ++k) {
                    float v = row[k];
                    hv[k] = __float2bfloat16_rn(v);
                    lv[k] = __float2bfloat16_rn(v - __bfloat162float(hv[k]));
                }
                __nv_bfloat16* H = s ? phH : thH;
                __nv_bfloat16* L = s ? phL : thL;
                size_t dst = ((size_t)b * NPIX + h0 * HW + p) * 64 + co_off + half * 16;
                *(uint4*)&H[dst]     = ((uint4*)hv)[0];
                *(uint4*)&H[dst + 8] = ((uint4*)hv)[1];
                *(uint4*)&L[dst]     = ((uint4*)lv)[0];
                *(uint4*)&L[dst + 8] = ((uint4*)lv)[1];
            }
        }
    }
}

__global__ void bnfinalize_kernel(const float* __restrict__ stats,
                                  float* __restrict__ mean, float* __restrict__ rstd)
{
    int c = threadIdx.x;
    const float invN = 1.f / (BATCH * NPIX);
    float m = stats[c] * invN;
    float v = stats[CH + c] * invN - m * m;
    mean[c] = m;
    rstd[c] = rsqrtf(v + EPSBN);
}

__global__ void __launch_bounds__(256) bnapply_kernel(
    const float* __restrict__ v, const float* __restrict__ mean,
    const float* __restrict__ rstd, const float* __restrict__ gamma,
    const float* __restrict__ beta, float* __restrict__ out)
{
    int i = blockIdx.x * 256 + threadIdx.x;
    int c = (i >> 12) & 63;
    float r = (v[i] - mean[c]) * rstd[c] * gamma[c] + beta[c];
    out[i] = fmaxf(r, 0.f);
}

// ---------------------------------------------------------------------------
// Fused attention, m-split x2: each CTA handles 2048 of m, emits partial
// unscaled y-sums + partial rowsums. 115.2KB smem -> 2 CTAs/SM, 256 CTAs.
// ---------------------------------------------------------------------------
#define FA_TH_HI 0
#define FA_TH_LO 16384
#define FA_BUF0  32768
#define FA_BUF1  65536
#define FA_PH    0
#define FA_PL    8192
#define FA_GH    16384
#define FA_GL    24576
#define FA_P     98304
#define FA_RS    114688
#define FA_SMEM  115200
#define EP_SY    0           // 128 x 65 f32 = 33280 (overlays TH + BUF0 head)

__global__ void __launch_bounds__(256, 2) attn_fused_kernel(
    const __nv_bfloat16* __restrict__ thT_hi, const __nv_bfloat16* __restrict__ thT_lo,
    const __nv_bfloat16* __restrict__ phT_hi, const __nv_bfloat16* __restrict__ phT_lo,
    const __nv_bfloat16* __restrict__ g_hi,   const __nv_bfloat16* __restrict__ g_lo,
    float* __restrict__ yp, float* __restrict__ rsp)
{
    extern __shared__ __align__(128) char smem[];
    const uint32_t sb = smem_u32(smem);
    const int tid = threadIdx.x, w = tid >> 5, lane = tid & 31;
    const int n0 = blockIdx.x * 128, b = blockIdx.y, part = blockIdx.z;
    const int wn = w & 3, wm = w >> 2;

    float* yp_p  = yp  + (size_t)part * (BATCH * CH * NPIX);
    float* rsp_p = rsp + part * (BATCH * NPIX);

    float* sRS = (float*)(smem + FA_RS);
    if (tid < 128) sRS[tid] = 0.f;

    {
        const uint4* Ah = (const uint4*)(thT_hi + ((size_t)b * NPIX + n0) * 64);
        const uint4* Al = (const uint4*)(thT_lo + ((size_t)b * NPIX + n0) * 64);
        for (int i = tid; i < 1024; i += 256) {
            uint32_t off = SW128((uint32_t)(i >> 3) * 128 + (i & 7) * 16);
            *(uint4*)(smem + FA_TH_HI + off) = Ah[i];
            *(uint4*)(smem + FA_TH_LO + off) = Al[i];
        }
    }

    const char* phh = (const char*)(phT_hi + (size_t)b * NPIX * 64);
    const char* phl = (const char*)(phT_lo + (size_t)b * NPIX * 64);

    // one 64-wide m-chunk: phi 64m x 64c hi/lo + g 64c x 64m hi/lo
    auto load_chunk = [&](int mb, uint32_t buf) {
        const char* ph = phh + (size_t)mb * 128;
        const char* pl = phl + (size_t)mb * 128;
        for (int i = tid; i < 512; i += 256) {
            uint32_t off = SW128((uint32_t)(i >> 3) * 128 + (i & 7) * 16);
            cpasync16(sb + buf + FA_PH + off, ph + i * 16);
            cpasync16(sb + buf + FA_PL + off, pl + i * 16);
        }
        for (int i = tid; i < 512; i += 256) {
            int row = i >> 3, seg = i & 7;
            uint32_t off = SW128((uint32_t)row * 128 + seg * 16);
            const size_t go = ((size_t)(b * CH + row)) * NPIX + mb + seg * 8;
            cpasync16(sb + buf + FA_GH + off, g_hi + go);
            cpasync16(sb + buf + FA_GL + off, g_lo + go);
        }
        cpasync_commit();
    };

    const int mbase = part << 11;   // 2048 per part
    load_chunk(mbase, FA_BUF0);
    cpasync_wait0();
    __syncthreads();

    float acco[2][4][4];
    #pragma unroll
    for (int i = 0; i < 2; ++i)
        #pragma unroll
        for (int j = 0; j < 4; ++j)
            #pragma unroll
            for (int k = 0; k < 4; ++k) acco[i][j][k] = 0.f;
    float rs[2][2] = {{0.f, 0.f}, {0.f, 0.f}};

    const int arow = (lane & 15), acol = (lane >> 4);
    const int brow = ((lane >> 4) << 3) + (lane & 7), bcol = ((lane >> 3) & 1);

    for (int c = 0; c < 32; ++c) {
        const uint32_t buf  = (c & 1) ? FA_BUF1 : FA_BUF0;
        const uint32_t nbuf = (c & 1) ? FA_BUF0 : FA_BUF1;
        if (c < 31) load_chunk(mbase + (c + 1) * 64, nbuf);

        // ---- S: 128n x 64m, K=64, 3-pass hi/lo. warp = 32n x 32m ----
        float accs[2][4][4];
        #pragma unroll
        for (int i = 0; i < 2; ++i)
            #pragma unroll
            for (int j = 0; j < 4; ++j)
                #pragma unroll
                for (int k = 0; k < 4; ++k) accs[i][j][k] = 0.f;

        #pragma unroll
        for (int k = 0; k < 4; ++k) {
            uint32_t aH[2][4], aL[2][4], bH[2][4], bL[2][4];
            #pragma unroll
            for (int fi = 0; fi < 2; ++fi) {
                uint32_t off = SW128((uint32_t)(wn * 32 + fi * 16 + arow) * 128 + (k * 2 + acol) * 16);
                ldsm4(aH[fi], sb + FA_TH_HI + off);
                ldsm4(aL[fi], sb + FA_TH_LO + off);
            }
            #pragma unroll
            for (int bq = 0; bq < 2; ++bq) {
                uint32_t off = SW128((uint32_t)(wm * 32 + bq * 16 + brow) * 128 + (k * 2 + bcol) * 16);
                ldsm4(bH[bq], sb + buf + FA_PH + off);
                ldsm4(bL[bq], sb + buf + FA_PL + off);
            }
            #pragma unroll
            for (int fi = 0; fi < 2; ++fi)
                #pragma unroll
                for (int bq = 0; bq < 2; ++bq) {
                    mma16816(accs[fi][2 * bq],     aH[fi], &bH[bq][0]);
                    mma16816(accs[fi][2 * bq + 1], aH[fi], &bH[bq][2]);
                    mma16816(accs[fi][2 * bq],     aH[fi], &bL[bq][0]);
                    mma16816(accs[fi][2 * bq + 1], aH[fi], &bL[bq][2]);
                    mma16816(accs[fi][2 * bq],     aL[fi], &bH[bq][0]);
                    mma16816(accs[fi][2 * bq + 1], aL[fi], &bH[bq][2]);
                }
        }

        // ---- exp (ex2, theta prescaled) -> P bf16 + rowsum ----
        #pragma unroll
        for (int fi = 0; fi < 2; ++fi) {
            const int n1 = wn * 32 + fi * 16 + (lane >> 2);
            #pragma unroll
            for (int bj = 0; bj < 4; ++bj) {
                const int ml = wm * 32 + bj * 8 + (lane & 3) * 2;
                float e0 = ex2f(accs[fi][bj][0]);
                float e1 = ex2f(accs[fi][bj][1]);
                float e2 = ex2f(accs[fi][bj][2]);
                float e3 = ex2f(accs[fi][bj][3]);
                rs[fi][0] += e0 + e1; rs[fi][1] += e2 + e3;
                __nv_bfloat162 p01 = __floats2bfloat162_rn(e0, e1);
                __nv_bfloat162 p23 = __floats2bfloat162_rn(e2, e3);
                *(uint32_t*)(smem + FA_P + SW128((uint32_t)n1 * 128 + ml * 2))       = *(uint32_t*)&p01;
                *(uint32_t*)(smem + FA_P + SW128((uint32_t)(n1 + 8) * 128 + ml * 2)) = *(uint32_t*)&p23;
            }
        }
        __syncthreads();

        // ---- PV: P(128n x 64m) @ g(64c x 64m)^T, 2-pass hi/lo ----
        #pragma unroll
        for (int kk = 0; kk < 4; ++kk) {
            uint32_t aP[2][4], bH2[2][4], bL2[2][4];
            #pragma unroll
            for (int fi = 0; fi < 2; ++fi) {
                uint32_t off = SW128((uint32_t)(wn * 32 + fi * 16 + arow) * 128 + (kk * 2 + acol) * 16);
                ldsm4(aP[fi], sb + FA_P + off);
            }
            #pragma unroll
            for (int cq = 0; cq < 2; ++cq) {
                uint32_t off = SW128((uint32_t)(wm * 32 + cq * 16 + brow) * 128 + (kk * 2 + bcol) * 16);
                ldsm4(bH2[cq], sb + buf + FA_GH + off);
                ldsm4(bL2[cq], sb + buf + FA_GL + off);
            }
            #pragma unroll
            for (int fi = 0; fi < 2; ++fi)
                #pragma unroll
                for (int cq = 0; cq < 2; ++cq) {
                    mma16816(acco[fi][2 * cq],     aP[fi], &bH2[cq][0]);
                    mma16816(acco[fi][2 * cq + 1], aP[fi], &bH2[cq][2]);
                    mma16816(acco[fi][2 * cq],     aP[fi], &bL2[cq][0]);
                    mma16816(acco[fi][2 * cq + 1], aP[fi], &bL2[cq][2]);
                }
        }

        cpasync_wait0();
        __syncthreads();
    }

    // ---- partial rowsum reduce ----
    #pragma unroll
    for (int fi = 0; fi < 2; ++fi) {
        const int n1 = wn * 32 + fi * 16 + (lane >> 2);
        float s1 = rs[fi][0], s2 = rs[fi][1];
        s1 += __shfl_xor_sync(0xffffffffu, s1, 1);
        s1 += __shfl_xor_sync(0xffffffffu, s1, 2);
        s2 += __shfl_xor_sync(0xffffffffu, s2, 1);
        s2 += __shfl_xor_sync(0xffffffffu, s2, 2);
        if ((lane & 3) == 0) {
            atomicAdd(&sRS[n1], s1);
            atomicAdd(&sRS[n1 + 8], s2);
        }
    }
    __syncthreads();

    // ---- store partial y (unscaled) via smem transpose + partial rowsums ----
    float* sY = (float*)(smem + EP_SY);
    #pragma unroll
    for (int fi = 0; fi < 2; ++fi) {
        int n1 = wn * 32 + fi * 16 + (lane >> 2);
        #pragma unroll
        for (int bj = 0; bj < 4; ++bj) {
            int cl = wm * 32 + bj * 8 + (lane & 3) * 2;
            sY[n1 * 65 + cl]           = acco[fi][bj][0];
            sY[n1 * 65 + cl + 1]       = acco[fi][bj][1];
            sY[(n1 + 8) * 65 + cl]     = acco[fi][bj][2];
            sY[(n1 + 8) * 65 + cl + 1] = acco[fi][bj][3];
        }
    }
    __syncthreads();
    if (tid < 128) rsp_p[b * NPIX + n0 + tid] = sRS[tid];
    for (int i = tid; i < 8192; i += 256) {
        int c = i >> 7, n = i & 127;
        yp_p[((size_t)(b * CH + c) << 12) + n0 + n] = sY[n * 65 + c];
    }
}

// ---------------------------------------------------------------------------
// Combine partials + 1x1 W conv + residual -> z
// ---------------------------------------------------------------------------
__global__ void __launch_bounds__(128) wcombine_kernel(
    const float* __restrict__ yp0, const float* __restrict__ yp1,
    const float* __restrict__ rs0, const float* __restrict__ rs1,
    const float* __restrict__ Ww, const float* __restrict__ Wb,
    const float* __restrict__ x, float* __restrict__ z)
{
    __shared__ float sW[CH * CH];
    __shared__ float sB[CH];
    const int tid = threadIdx.x;
    for (int i = tid; i < CH * CH; i += 128) sW[i] = Ww[i];
    if (tid < CH) sB[tid] = Wb[tid];
    __syncthreads();

    const int pix = blockIdx.x * 128 + tid;
    const int b = pix >> 12, n = pix & 4095;

    float inv = 1.f / (rs0[b * NPIX + n] + rs1[b * NPIX + n]);
    float yv[CH];
    #pragma unroll
    for (int ci = 0; ci < CH; ++ci) {
        size_t o = (size_t)(b * CH + ci) * NPIX + n;
        yv[ci] = (yp0[o] + yp1[o]) * inv;
    }

    #pragma unroll 1
    for (int co = 0; co < CH; ++co) {
        float acc = sB[co];
        #pragma unroll
        for (int ci = 0; ci < CH; ++ci) acc += sW[co * CH + ci] * yv[ci];
        size_t o = (size_t)(b * CH + co) * NPIX + n;
        z[o] = acc + x[o];
    }
}

// ---------------------------------------------------------------------------
// Launch
// ---------------------------------------------------------------------------
extern "C" void kernel_launch(void* const* d_in, const int* in_sizes, int n_in,
                              void* d_out, int out_size)
{
    const float* x       = (const float*)d_in[0];
    const float* conv1_w = (const float*)d_in[1];
    const float* bn1_g   = (const float*)d_in[2];
    const float* bn1_b   = (const float*)d_in[3];
    const float* theta_w = (const float*)d_in[4];
    const float* theta_b = (const float*)d_in[5];
    const float* phi_w   = (const float*)d_in[6];
    const float* phi_b   = (const float*)d_in[7];
    const float* gw      = (const float*)d_in[8];
    const float* gb      = (const float*)d_in[9];
    const float* W_w     = (const float*)d_in[10];
    const float* W_b     = (const float*)d_in[11];
    const float* conv2_w = (const float*)d_in[12];
    const float* bn2_g   = (const float*)d_in[13];
    const float* bn2_b   = (const float*)d_in[14];
    float* out = (float*)d_out;

    float *p_c1, *p_z, *p_mean, *p_rstd, *p_stats, *p_yp, *p_rsp;
    __nv_bfloat16 *p_wm, *p_thH, *p_thL, *p_phH, *p_phL, *p_gH, *p_gL;
    cudaGetSymbolAddress((void**)&p_c1,   g_c1raw);
    cudaGetSymbolAddress((void**)&p_z,    g_z);
    cudaGetSymbolAddress((void**)&p_mean, g_mean);
    cudaGetSymbolAddress((void**)&p_rstd, g_rstd);
    cudaGetSymbolAddress((void**)&p_stats, g_stats);
    cudaGetSymbolAddress((void**)&p_yp,   g_ypart);
    cudaGetSymbolAddress((void**)&p_rsp,  g_rspart);
    cudaGetSymbolAddress((void**)&p_wm,   g_wmma);
    cudaGetSymbolAddress((void**)&p_thH,  g_thT_hi);
    cudaGetSymbolAddress((void**)&p_thL,  g_thT_lo);
    cudaGetSymbolAddress((void**)&p_phH,  g_phT_hi);
    cudaGetSymbolAddress((void**)&p_phL,  g_phT_lo);
    cudaGetSymbolAddress((void**)&p_gH,   g_g_hi);
    cudaGetSymbolAddress((void**)&p_gL,   g_g_lo);

    cudaFuncSetAttribute(conv_mma_kernel<0>, cudaFuncAttributeMaxDynamicSharedMemorySize, CV_SMEM0);
    cudaFuncSetAttribute(conv_mma_kernel<1>, cudaFuncAttributeMaxDynamicSharedMemorySize, CV_SMEM1);
    cudaFuncSetAttribute(attn_fused_kernel,  cudaFuncAttributeMaxDynamicSharedMemorySize, FA_SMEM);

    wtrans_mma_kernel<<<720, 256>>>(conv1_w, theta_w, phi_w, gw, conv2_w, p_wm);

    // conv1 (+BN1 stats)
    cudaMemsetAsync(p_stats, 0, 2 * CH * sizeof(float));
    conv_mma_kernel<0><<<dim3(32, BATCH, 2), 256, CV_SMEM0>>>(
        x, p_wm, p_c1, p_stats,
        nullptr, nullptr, nullptr, nullptr, nullptr, nullptr, nullptr,
        nullptr, nullptr, nullptr, nullptr, nullptr, nullptr);
    bnfinalize_kernel<<<1, 64>>>(p_stats, p_mean, p_rstd);

    // fused projections (BN1 on input; direct bf16 hi/lo outputs; theta*log2e)
    conv_mma_kernel<1><<<dim3(32, BATCH, 2), 256, CV_SMEM1>>>(
        p_c1, p_wm + (size_t)9 * 2 * 4096, nullptr, nullptr,
        p_mean, p_rstd, bn1_g, bn1_b, theta_b, phi_b, gb,
        p_thH, p_thL, p_phH, p_phL, p_gH, p_gL);

    // fused attention, m-split x2 -> partials
    attn_fused_kernel<<<dim3(32, BATCH, 2), 256, FA_SMEM>>>(
        p_thH, p_thL, p_phH, p_phL, p_gH, p_gL, p_yp, p_rsp);

    // combine + 1x1 W conv + residual -> z
    wcombine_kernel<<<(BATCH * NPIX) / 128, 128>>>(
        p_yp, p_yp + (size_t)BATCH * CH * NPIX, p_rsp, p_rsp + BATCH * NPIX,
        W_w, W_b, x, p_z);

    // conv2 (+BN2 stats) + final BN apply
    cudaMemsetAsync(p_stats, 0, 2 * CH * sizeof(float));
    conv_mma_kernel<0><<<dim3(32, BATCH, 2), 256, CV_SMEM0>>>(
        p_z, p_wm + (size_t)4 * 9 * 2 * 4096, p_c1, p_stats,
        nullptr, nullptr, nullptr, nullptr, nullptr, nullptr, nullptr,
        nullptr, nullptr, nullptr, nullptr, nullptr, nullptr);
    bnfinalize_kernel<<<1, 64>>>(p_stats, p_mean, p_rstd);
    bnapply_kernel<<<(BATCH * CH * NPIX) / 256, 256>>>(p_c1, p_mean, p_rstd, bn2_g, bn2_b, out);
}